// round 16
// baseline (speedup 1.0000x reference)
#include <cuda_runtime.h>

#define NROWS  8192
#define DCOLS  4096
#define MARGINF 5.0f
#define MAXLIST 2048
#define DTHREADS 256
#define RPB 8                       // rows per block (one per warp)
#define NBLOCKS (NROWS / RPB)       // 1024

// Scratch. g_ticket's initial value matches the reset done by the last
// block, so every graph replay starts from identical state. No other
// cross-block state exists (stats are computed by the last block itself).
__device__ float        g_d[NROWS];
__device__ unsigned int g_ticket = 0u;

// Warp-per-row distance kernel, NO global stats atomics (the f64 REDG
// streams to single addresses were serializing ~131K LTS cycles and
// halving chip bandwidth in earlier fused variants). Each warp privately
// reduces one row; block releases one int ticket. The LAST block acquires
// and finalizes everything:
//   Sum_{i pos, j neg} max(0, d_i-d_j+M)
// = [Nn*Sp - Np*Sn + M*Np*Nn] + Sum max(0, d_j - d_i - M)
// Pass A computes Sp/Sn/Np/min/max from g_d (L2-hot, vectorized).
// Pass B gathers hinge-overflow candidates (pos with d_i < max_neg-M,
// neg with d_j > min_pos+M; ~330 each) — L1-hot. Exact pos-striped
// cross-product correction, then output + ticket reset.
__global__ __launch_bounds__(DTHREADS) void dist_kernel(
    const float* __restrict__ recon, const float* __restrict__ x,
    const int* __restrict__ targets, float* __restrict__ out)
{
    const int tid  = threadIdx.x;
    const int lane = tid & 31;
    const int wid  = tid >> 5;
    const int row  = blockIdx.x * RPB + wid;

    const float4* r4 = reinterpret_cast<const float4*>(recon + (size_t)row * DCOLS);
    const float4* x4 = reinterpret_cast<const float4*>(x + (size_t)row * DCOLS);

    float acc = 0.0f;
    #pragma unroll 8
    for (int k = lane; k < DCOLS / 4; k += 32) {   // 32 iters, 512B/warp-load
        float4 a = r4[k];
        float4 b = x4[k];
        float d0 = a.x - b.x;
        float d1 = a.y - b.y;
        float d2 = a.z - b.z;
        float d3 = a.w - b.w;
        acc = fmaf(d0, d0, acc);
        acc = fmaf(d1, d1, acc);
        acc = fmaf(d2, d2, acc);
        acc = fmaf(d3, d3, acc);
    }

    #pragma unroll
    for (int o = 16; o > 0; o >>= 1)
        acc += __shfl_xor_sync(0xFFFFFFFFu, acc, o);

    if (lane == 0)
        g_d[row] = sqrtf(acc) + 0.001f;
    __syncthreads();

    __shared__ int s_last;
    if (tid == 0) {
        // Release-ordered ticket: publishes this block's g_d writes
        // (ordered by the bar.sync above) without a MEMBAR.
        unsigned int one = 1u, t;
        asm volatile("atom.release.gpu.global.add.u32 %0, [%1], %2;"
                     : "=r"(t) : "l"(&g_ticket), "r"(one) : "memory");
        s_last = (t == NBLOCKS - 1);
    }
    __syncthreads();
    if (!s_last) return;

    // ================= last block: fused finalize =================
    asm volatile("fence.acq_rel.gpu;" ::: "memory");

    __shared__ double rSp[8], rSn[8];
    __shared__ float  rMn[8], rMx[8];
    __shared__ int    rNp[8];
    __shared__ float  s_thrP, s_thrN;
    __shared__ double s_Sp, s_Sn;
    __shared__ int    s_np;
    __shared__ float  posList[MAXLIST], negList[MAXLIST];
    __shared__ int    s_npl, s_nnl;
    __shared__ double redC[8];

    if (tid == 0) { s_npl = 0; s_nnl = 0; }

    // ---- Pass A: stats over all rows (vectorized, L2-hot) ----
    const float4* d4 = reinterpret_cast<const float4*>(g_d);
    const int4*   t4 = reinterpret_cast<const int4*>(targets);

    double sp = 0.0, sn = 0.0;
    float  mnp = 1.0e30f, mxn = -1.0e30f;
    int np = 0;
    #pragma unroll
    for (int k = tid; k < NROWS / 4; k += DTHREADS) {   // 8 iters
        float4 dv = d4[k];
        int4   tv = t4[k];
        if (tv.x == 1) { sp += (double)dv.x; mnp = fminf(mnp, dv.x); np++; }
        else           { sn += (double)dv.x; mxn = fmaxf(mxn, dv.x); }
        if (tv.y == 1) { sp += (double)dv.y; mnp = fminf(mnp, dv.y); np++; }
        else           { sn += (double)dv.y; mxn = fmaxf(mxn, dv.y); }
        if (tv.z == 1) { sp += (double)dv.z; mnp = fminf(mnp, dv.z); np++; }
        else           { sn += (double)dv.z; mxn = fmaxf(mxn, dv.z); }
        if (tv.w == 1) { sp += (double)dv.w; mnp = fminf(mnp, dv.w); np++; }
        else           { sn += (double)dv.w; mxn = fmaxf(mxn, dv.w); }
    }
    #pragma unroll
    for (int o = 16; o > 0; o >>= 1) {
        sp  += __shfl_xor_sync(0xFFFFFFFFu, sp, o);
        sn  += __shfl_xor_sync(0xFFFFFFFFu, sn, o);
        mnp  = fminf(mnp, __shfl_xor_sync(0xFFFFFFFFu, mnp, o));
        mxn  = fmaxf(mxn, __shfl_xor_sync(0xFFFFFFFFu, mxn, o));
        np  += __shfl_xor_sync(0xFFFFFFFFu, np, o);
    }
    if (lane == 0) {
        rSp[wid] = sp; rSn[wid] = sn;
        rMn[wid] = mnp; rMx[wid] = mxn; rNp[wid] = np;
    }
    __syncthreads();
    if (tid == 0) {
        double bsp = 0.0, bsn = 0.0;
        float  bmn = 1.0e30f, bmx = -1.0e30f;
        int bnp = 0;
        #pragma unroll
        for (int w = 0; w < 8; w++) {
            bsp += rSp[w]; bsn += rSn[w];
            bmn = fminf(bmn, rMn[w]); bmx = fmaxf(bmx, rMx[w]);
            bnp += rNp[w];
        }
        s_Sp = bsp; s_Sn = bsn; s_np = bnp;
        s_thrP = bmx - MARGINF;   // pos matter if d_i < thrP
        s_thrN = bmn + MARGINF;   // neg matter if d_j > thrN
    }
    __syncthreads();

    const float thrP = s_thrP;
    const float thrN = s_thrN;

    // ---- Pass B: gather hinge-overflow candidates (L1-hot) ----
    #pragma unroll
    for (int k = tid; k < NROWS / 4; k += DTHREADS) {
        float4 dv = d4[k];
        int4   tv = t4[k];
        #pragma unroll
        for (int e = 0; e < 4; e++) {
            float d = (e == 0) ? dv.x : (e == 1) ? dv.y : (e == 2) ? dv.z : dv.w;
            int   t = (e == 0) ? tv.x : (e == 1) ? tv.y : (e == 2) ? tv.z : tv.w;
            if (t == 1) {
                if (d < thrP) {
                    int idx = atomicAdd(&s_npl, 1);
                    if (idx < MAXLIST) posList[idx] = d;
                }
            } else {
                if (d > thrN) {
                    int idx = atomicAdd(&s_nnl, 1);
                    if (idx < MAXLIST) negList[idx] = d;
                }
            }
        }
    }
    __syncthreads();

    const int npl = min(s_npl, MAXLIST);
    const int nnl = min(s_nnl, MAXLIST);

    // ---- Exact correction: pos-striped, neg list serial per pos ----
    float corrF = 0.0f;
    for (int ip = tid; ip < npl; ip += DTHREADS) {
        const float dp = posList[ip] + MARGINF;
        float a = 0.0f;
        for (int jn = 0; jn < nnl; jn++) {
            a += fmaxf(negList[jn] - dp, 0.0f);
        }
        corrF += a;
    }
    double corr = (double)corrF;
    #pragma unroll
    for (int o = 16; o > 0; o >>= 1)
        corr += __shfl_xor_sync(0xFFFFFFFFu, corr, o);
    if (lane == 0) redC[wid] = corr;
    __syncthreads();

    if (tid == 0) {
        double c = 0.0;
        #pragma unroll
        for (int w = 0; w < 8; w++) c += redC[w];
        double Np = (double)s_np;
        double Nn = (double)(NROWS - s_np);
        double linear = Nn * s_Sp - Np * s_Sn + (double)MARGINF * Np * Nn;
        out[0] = (float)((linear + c) / (Np * Nn));
        g_ticket = 0u;   // reset for next graph replay
    }
}

extern "C" void kernel_launch(void* const* d_in, const int* in_sizes, int n_in,
                              void* d_out, int out_size)
{
    const float* recon   = (const float*)d_in[0];
    const float* x       = (const float*)d_in[1];
    const int*   targets = (const int*)d_in[2];
    float* out = (float*)d_out;

    dist_kernel<<<NBLOCKS, DTHREADS>>>(recon, x, targets, out);
}

// round 17
// speedup vs baseline: 1.0584x; 1.0584x over previous
#include <cuda_runtime.h>

#define NROWS  8192
#define DCOLS  4096
#define MARGINF 5.0f
#define MAXLIST 1024
#define DTHREADS 256
#define RPB 8                       // rows per block (one per warp)
#define NBLOCKS (NROWS / RPB)       // 1024

// Scratch. g_ticket's initial value matches the reset done by the last
// block, so every graph replay starts from identical state. No other
// cross-block state exists (stats are computed by the last block itself).
__device__ float        g_d[NROWS];
__device__ unsigned int g_ticket = 0u;

// Warp-per-row distance kernel + last-block finalize.
// __launch_bounds__(256, 8) pins the register budget to 32/thread so the
// rarely-executed finalize tail (spilled to local) cannot deflate the hot
// loop's occupancy (R16: regs=80 -> occ 34% -> DRAM 50%).
// No global stats atomics (f64 same-address REDG serialized the LTS in
// R10-R14). One int release-ticket per block; the last block acquires and:
//   Sum_{i pos, j neg} max(0, d_i-d_j+M)
// = [Nn*Sp - Np*Sn + M*Np*Nn] + Sum max(0, d_j - d_i - M)
// Pass A: stats (Sp/Sn/Np/min/max) over g_d. Pass B: gather hinge-overflow
// candidates (pos with d_i < max_neg-M, neg with d_j > min_pos+M; ~330
// each). Exact pos-striped cross-product correction, output, ticket reset.
__global__ __launch_bounds__(DTHREADS, 8) void dist_kernel(
    const float* __restrict__ recon, const float* __restrict__ x,
    const int* __restrict__ targets, float* __restrict__ out)
{
    const int tid  = threadIdx.x;
    const int lane = tid & 31;
    const int wid  = tid >> 5;
    const int row  = blockIdx.x * RPB + wid;

    const float4* r4 = reinterpret_cast<const float4*>(recon + (size_t)row * DCOLS);
    const float4* x4 = reinterpret_cast<const float4*>(x + (size_t)row * DCOLS);

    float acc = 0.0f;
    #pragma unroll 4
    for (int k = lane; k < DCOLS / 4; k += 32) {   // 32 iters, 512B/warp-load
        float4 a = r4[k];
        float4 b = x4[k];
        float d0 = a.x - b.x;
        float d1 = a.y - b.y;
        float d2 = a.z - b.z;
        float d3 = a.w - b.w;
        acc = fmaf(d0, d0, acc);
        acc = fmaf(d1, d1, acc);
        acc = fmaf(d2, d2, acc);
        acc = fmaf(d3, d3, acc);
    }

    #pragma unroll
    for (int o = 16; o > 0; o >>= 1)
        acc += __shfl_xor_sync(0xFFFFFFFFu, acc, o);

    if (lane == 0)
        g_d[row] = sqrtf(acc) + 0.001f;
    __syncthreads();

    __shared__ int s_last;
    if (tid == 0) {
        // Release-ordered ticket: publishes this block's g_d writes
        // (ordered by the bar.sync above) without a MEMBAR.
        unsigned int one = 1u, t;
        asm volatile("atom.release.gpu.global.add.u32 %0, [%1], %2;"
                     : "=r"(t) : "l"(&g_ticket), "r"(one) : "memory");
        s_last = (t == NBLOCKS - 1);
    }
    __syncthreads();
    if (!s_last) return;

    // ================= last block: fused finalize =================
    // (cold path; may spill — runs once on one SM)
    asm volatile("fence.acq_rel.gpu;" ::: "memory");

    __shared__ double rSp[8], rSn[8];
    __shared__ float  rMn[8], rMx[8];
    __shared__ int    rNp[8];
    __shared__ float  s_thrP, s_thrN;
    __shared__ double s_Sp, s_Sn;
    __shared__ int    s_np;
    __shared__ float  posList[MAXLIST], negList[MAXLIST];
    __shared__ int    s_npl, s_nnl;
    __shared__ double redC[8];

    if (tid == 0) { s_npl = 0; s_nnl = 0; }

    // ---- Pass A: stats over all rows (scalar, L2-hot) ----
    double sp = 0.0, sn = 0.0;
    float  mnp = 1.0e30f, mxn = -1.0e30f;
    int np = 0;
    for (int k = tid; k < NROWS; k += DTHREADS) {   // 32 iters
        float dv = g_d[k];
        if (targets[k] == 1) {
            sp += (double)dv; mnp = fminf(mnp, dv); np++;
        } else {
            sn += (double)dv; mxn = fmaxf(mxn, dv);
        }
    }
    #pragma unroll
    for (int o = 16; o > 0; o >>= 1) {
        sp  += __shfl_xor_sync(0xFFFFFFFFu, sp, o);
        sn  += __shfl_xor_sync(0xFFFFFFFFu, sn, o);
        mnp  = fminf(mnp, __shfl_xor_sync(0xFFFFFFFFu, mnp, o));
        mxn  = fmaxf(mxn, __shfl_xor_sync(0xFFFFFFFFu, mxn, o));
        np  += __shfl_xor_sync(0xFFFFFFFFu, np, o);
    }
    if (lane == 0) {
        rSp[wid] = sp; rSn[wid] = sn;
        rMn[wid] = mnp; rMx[wid] = mxn; rNp[wid] = np;
    }
    __syncthreads();
    if (tid == 0) {
        double bsp = 0.0, bsn = 0.0;
        float  bmn = 1.0e30f, bmx = -1.0e30f;
        int bnp = 0;
        #pragma unroll
        for (int w = 0; w < 8; w++) {
            bsp += rSp[w]; bsn += rSn[w];
            bmn = fminf(bmn, rMn[w]); bmx = fmaxf(bmx, rMx[w]);
            bnp += rNp[w];
        }
        s_Sp = bsp; s_Sn = bsn; s_np = bnp;
        s_thrP = bmx - MARGINF;   // pos matter if d_i < thrP
        s_thrN = bmn + MARGINF;   // neg matter if d_j > thrN
    }
    __syncthreads();

    const float thrP = s_thrP;
    const float thrN = s_thrN;

    // ---- Pass B: gather hinge-overflow candidates (L1-hot) ----
    for (int k = tid; k < NROWS; k += DTHREADS) {
        float dv = g_d[k];
        if (targets[k] == 1) {
            if (dv < thrP) {
                int idx = atomicAdd(&s_npl, 1);
                if (idx < MAXLIST) posList[idx] = dv;
            }
        } else {
            if (dv > thrN) {
                int idx = atomicAdd(&s_nnl, 1);
                if (idx < MAXLIST) negList[idx] = dv;
            }
        }
    }
    __syncthreads();

    const int npl = min(s_npl, MAXLIST);
    const int nnl = min(s_nnl, MAXLIST);

    // ---- Exact correction: pos-striped, neg list serial per pos ----
    float corrF = 0.0f;
    for (int ip = tid; ip < npl; ip += DTHREADS) {
        const float dp = posList[ip] + MARGINF;
        float a = 0.0f;
        for (int jn = 0; jn < nnl; jn++) {
            a += fmaxf(negList[jn] - dp, 0.0f);
        }
        corrF += a;
    }
    double corr = (double)corrF;
    #pragma unroll
    for (int o = 16; o > 0; o >>= 1)
        corr += __shfl_xor_sync(0xFFFFFFFFu, corr, o);
    if (lane == 0) redC[wid] = corr;
    __syncthreads();

    if (tid == 0) {
        double c = 0.0;
        #pragma unroll
        for (int w = 0; w < 8; w++) c += redC[w];
        double Np = (double)s_np;
        double Nn = (double)(NROWS - s_np);
        double linear = Nn * s_Sp - Np * s_Sn + (double)MARGINF * Np * Nn;
        out[0] = (float)((linear + c) / (Np * Nn));
        g_ticket = 0u;   // reset for next graph replay
    }
}

extern "C" void kernel_launch(void* const* d_in, const int* in_sizes, int n_in,
                              void* d_out, int out_size)
{
    const float* recon   = (const float*)d_in[0];
    const float* x       = (const float*)d_in[1];
    const int*   targets = (const int*)d_in[2];
    float* out = (float*)d_out;

    dist_kernel<<<NBLOCKS, DTHREADS>>>(recon, x, targets, out);
}